// round 7
// baseline (speedup 1.0000x reference)
#include <cuda_runtime.h>
#include <cuda_bf16.h>
#include <math.h>

#define H 512
#define W 512
#define BATCH 16
#define NPIX (H*W)
#define CA 0.955f
#define CB 1.3693f
#define CINF 1e6f
#define BIG 1e30f

#define LBLK 256
#define BPI 16
#define NLB (BATCH*BPI)

// ---------------- device scratch ----------------
__device__ float    g_dist[BATCH*NPIX];
__device__ float    g_mx[BATCH];
__device__ int      g_flags[BATCH];
__device__ float    g_part[NLB*5];
__device__ unsigned g_seed[BATCH*H*16];   // 512 KB seed bitmaps

// =============== seed kernel: bitmap + dilate/erode -> seed bits ===============
__global__ __launch_bounds__(128) void seed_kernel(const int* __restrict__ target) {
    __shared__ unsigned mbits[H * 18];     // guard-padded mask bitmap (36 KB)
    __shared__ int sflag[2];

    const int img = blockIdx.x;
    const int* tg = target + img * NPIX;
    unsigned* sb = g_seed + img * H * 16;

    const int tid  = threadIdx.x;
    const int lane = tid & 31;
    const int sl   = tid & 7;
    const int sg   = tid >> 3;
    const int col0 = tid * 4;
    const unsigned FM = 0xffffffffu;

    if (tid < 2) sflag[tid] = 0;
    for (int r = tid; r < H; r += 128) {
        mbits[r * 18 + 0]  = 0u;
        mbits[r * 18 + 17] = 0u;
    }
    __syncthreads();

    bool any1 = false, any0 = false;
    for (int r = 0; r < H; r++) {
        int4 tv = *(const int4*)(tg + r * W + col0);
        unsigned nib = (unsigned)(tv.x != 0) | ((unsigned)(tv.y != 0) << 1)
                     | ((unsigned)(tv.z != 0) << 2) | ((unsigned)(tv.w != 0) << 3);
        any1 |= (nib != 0u);
        any0 |= (nib != 15u);
        unsigned word = nib << (4 * sl);
        word |= __shfl_xor_sync(FM, word, 1);
        word |= __shfl_xor_sync(FM, word, 2);
        word |= __shfl_xor_sync(FM, word, 4);
        if (sl == 0) mbits[r * 18 + 1 + sg] = word;
    }
    if (__any_sync(FM, any1) && lane == 0) atomicOr(&sflag[0], 1);
    if (__any_sync(FM, any0) && lane == 0) atomicOr(&sflag[1], 1);
    __syncthreads();
    const int hasb = sflag[0] & sflag[1];

    for (int idx = tid; idx < H * 16; idx += 128) {
        int r = idx >> 4, w = idx & 15;
        unsigned swd;
        if (hasb) {
            unsigned dil = 0u, ero = 0xffffffffu;
            #pragma unroll
            for (int dr = -1; dr <= 1; dr++) {
                int r2 = r + dr;
                if (r2 < 0 || r2 >= H) continue;
                unsigned M  = mbits[r2 * 18 + 1 + w];
                unsigned Ml = mbits[r2 * 18 + w];
                unsigned Mr = mbits[r2 * 18 + 2 + w];
                unsigned Mlg = (w == 0)  ? 0xffffffffu : Ml;
                unsigned Mrg = (w == 15) ? 0xffffffffu : Mr;
                dil |= M | __funnelshift_l(Ml, M, 1) | __funnelshift_r(M, Mr, 1);
                ero &= M & __funnelshift_l(Mlg, M, 1) & __funnelshift_r(M, Mrg, 1);
            }
            swd = dil & ~ero;
        } else {
            swd = ~mbits[r * 18 + 1 + w];
        }
        sb[idx] = swd;
    }
    if (tid == 0) g_flags[img] = sflag[0] | (sflag[1] << 1);
}

// =============== dt kernel: 16 warps pipelined over rows, 1 block/image ===============
__global__ __launch_bounds__(512) void dt_pipe_kernel() {
    __shared__ float ring[16][W];          // 32 KB: one published row per warp slot
    __shared__ volatile int flg[16];
    __shared__ float lred[16];

    const int img = blockIdx.x;
    const unsigned* sb = g_seed + img * H * 16;
    float* dd = g_dist + img * NPIX;

    const int t  = threadIdx.x & 31;       // lane
    const int w  = threadIdx.x >> 5;       // warp 0..15
    const int sp = (w + 15) & 15;          // predecessor slot
    const int c0 = t * 16;
    const unsigned FM = 0xffffffffu;

    if (threadIdx.x < 16) flg[threadIdx.x] = 0;
    __syncthreads();

    float aj[16];
    #pragma unroll
    for (int c = 0; c < 16; c++) aj[c] = CA * (float)(c0 + c);

    // ================= forward pass =================
    for (int b = 0; b < H / 16; b++) {
        const int r = w + 16 * b;
        unsigned hw = (sb[r * 16 + (t >> 1)] >> ((t & 1) * 16)) & 0xffffu;  // prefetch

        float p[16], pvL, pvR;
        if (r == 0) {
            #pragma unroll
            for (int c = 0; c < 16; c++) p[c] = CINF;
            pvL = CINF; pvR = CINF;
        } else {
            if (t == 0) { while (flg[sp] < r) {} }
            __syncwarp();
            __threadfence_block();
            float4 a0 = *(const float4*)&ring[sp][c0 + 0];
            float4 a1 = *(const float4*)&ring[sp][c0 + 4];
            float4 a2 = *(const float4*)&ring[sp][c0 + 8];
            float4 a3 = *(const float4*)&ring[sp][c0 + 12];
            p[0]=a0.x; p[1]=a0.y; p[2]=a0.z; p[3]=a0.w;
            p[4]=a1.x; p[5]=a1.y; p[6]=a1.z; p[7]=a1.w;
            p[8]=a2.x; p[9]=a2.y; p[10]=a2.z; p[11]=a2.w;
            p[12]=a3.x; p[13]=a3.y; p[14]=a3.z; p[15]=a3.w;
            pvL = __shfl_up_sync(FM, p[15], 1);  if (t == 0)  pvL = CINF;
            pvR = __shfl_down_sync(FM, p[0], 1); if (t == 31) pvR = CINF;
        }

        float v[16];
        #pragma unroll
        for (int c = 0; c < 16; c++) {
            float pl = (c == 0)  ? pvL : p[c - 1];
            float pr = (c == 15) ? pvR : p[c + 1];
            float d  = ((hw >> c) & 1u) ? 0.0f : CINF;
            float m = fminf(fminf(d, p[c] + CA), fminf(pl + CB, pr + CB));
            v[c] = m - aj[c];
        }
        #pragma unroll
        for (int off = 1; off < 16; off <<= 1)
            #pragma unroll
            for (int c = 15; c >= off; c--)
                v[c] = fminf(v[c], v[c - off]);

        float s = v[15], o;
        o = __shfl_up_sync(FM, s, 1);  if (t >= 1)  s = fminf(s, o);
        o = __shfl_up_sync(FM, s, 2);  if (t >= 2)  s = fminf(s, o);
        o = __shfl_up_sync(FM, s, 4);  if (t >= 4)  s = fminf(s, o);
        o = __shfl_up_sync(FM, s, 8);  if (t >= 8)  s = fminf(s, o);
        o = __shfl_up_sync(FM, s, 16); if (t >= 16) s = fminf(s, o);
        float excl = __shfl_up_sync(FM, s, 1);
        if (t == 0) excl = BIG;

        #pragma unroll
        for (int c = 0; c < 16; c++) p[c] = aj[c] + fminf(excl, v[c]);

        *(float4*)&ring[w][c0 + 0]  = make_float4(p[0],  p[1],  p[2],  p[3]);
        *(float4*)&ring[w][c0 + 4]  = make_float4(p[4],  p[5],  p[6],  p[7]);
        *(float4*)&ring[w][c0 + 8]  = make_float4(p[8],  p[9],  p[10], p[11]);
        *(float4*)&ring[w][c0 + 12] = make_float4(p[12], p[13], p[14], p[15]);
        float* row = dd + r * W + c0;
        *(float4*)(row + 0)  = make_float4(p[0],  p[1],  p[2],  p[3]);
        *(float4*)(row + 4)  = make_float4(p[4],  p[5],  p[6],  p[7]);
        *(float4*)(row + 8)  = make_float4(p[8],  p[9],  p[10], p[11]);
        *(float4*)(row + 12) = make_float4(p[12], p[13], p[14], p[15]);

        __syncwarp();
        __threadfence_block();
        if (t == 0) flg[w] = r + 1;
    }

    __syncthreads();
    if (threadIdx.x < 16) flg[threadIdx.x] = 0;
    __syncthreads();

    // ================= backward pass =================
    float ar[16];
    #pragma unroll
    for (int c = 0; c < 16; c++) ar[c] = CA * (float)(W - 1 - (c0 + c));
    float lmax = 0.0f;

    for (int b = 0; b < H / 16; b++) {
        const int k = w + 16 * b;          // processing order index
        const int r = H - 1 - k;           // actual row

        // prefetch forward-pass row (fixed since __syncthreads)
        const float* rowr = dd + r * W + c0;
        float4 d0 = *(const float4*)(rowr + 0);
        float4 d1 = *(const float4*)(rowr + 4);
        float4 d2 = *(const float4*)(rowr + 8);
        float4 d3 = *(const float4*)(rowr + 12);
        float drw[16] = {d0.x,d0.y,d0.z,d0.w, d1.x,d1.y,d1.z,d1.w,
                         d2.x,d2.y,d2.z,d2.w, d3.x,d3.y,d3.z,d3.w};

        float p[16], pvL, pvR;
        if (k == 0) {
            #pragma unroll
            for (int c = 0; c < 16; c++) p[c] = CINF;
            pvL = CINF; pvR = CINF;
        } else {
            if (t == 0) { while (flg[sp] < k) {} }
            __syncwarp();
            __threadfence_block();
            float4 a0 = *(const float4*)&ring[sp][c0 + 0];
            float4 a1 = *(const float4*)&ring[sp][c0 + 4];
            float4 a2 = *(const float4*)&ring[sp][c0 + 8];
            float4 a3 = *(const float4*)&ring[sp][c0 + 12];
            p[0]=a0.x; p[1]=a0.y; p[2]=a0.z; p[3]=a0.w;
            p[4]=a1.x; p[5]=a1.y; p[6]=a1.z; p[7]=a1.w;
            p[8]=a2.x; p[9]=a2.y; p[10]=a2.z; p[11]=a2.w;
            p[12]=a3.x; p[13]=a3.y; p[14]=a3.z; p[15]=a3.w;
            pvL = __shfl_up_sync(FM, p[15], 1);  if (t == 0)  pvL = CINF;
            pvR = __shfl_down_sync(FM, p[0], 1); if (t == 31) pvR = CINF;
        }

        float v[16];
        #pragma unroll
        for (int c = 0; c < 16; c++) {
            float pl = (c == 0)  ? pvL : p[c - 1];
            float pr = (c == 15) ? pvR : p[c + 1];
            float m = fminf(fminf(drw[c], p[c] + CA), fminf(pl + CB, pr + CB));
            v[c] = m - ar[c];
        }
        #pragma unroll
        for (int off = 1; off < 16; off <<= 1)
            #pragma unroll
            for (int c = 0; c <= 15 - off; c++)
                v[c] = fminf(v[c], v[c + off]);

        float s = v[0], o;
        o = __shfl_down_sync(FM, s, 1);  if (t <= 30) s = fminf(s, o);
        o = __shfl_down_sync(FM, s, 2);  if (t <= 29) s = fminf(s, o);
        o = __shfl_down_sync(FM, s, 4);  if (t <= 27) s = fminf(s, o);
        o = __shfl_down_sync(FM, s, 8);  if (t <= 23) s = fminf(s, o);
        o = __shfl_down_sync(FM, s, 16); if (t <= 15) s = fminf(s, o);
        float excl = __shfl_down_sync(FM, s, 1);
        if (t == 31) excl = BIG;

        #pragma unroll
        for (int c = 0; c < 16; c++) {
            p[c] = ar[c] + fminf(excl, v[c]);
            lmax = fmaxf(lmax, p[c]);
        }

        *(float4*)&ring[w][c0 + 0]  = make_float4(p[0],  p[1],  p[2],  p[3]);
        *(float4*)&ring[w][c0 + 4]  = make_float4(p[4],  p[5],  p[6],  p[7]);
        *(float4*)&ring[w][c0 + 8]  = make_float4(p[8],  p[9],  p[10], p[11]);
        *(float4*)&ring[w][c0 + 12] = make_float4(p[12], p[13], p[14], p[15]);
        float* roww = dd + r * W + c0;
        *(float4*)(roww + 0)  = make_float4(p[0],  p[1],  p[2],  p[3]);
        *(float4*)(roww + 4)  = make_float4(p[4],  p[5],  p[6],  p[7]);
        *(float4*)(roww + 8)  = make_float4(p[8],  p[9],  p[10], p[11]);
        *(float4*)(roww + 12) = make_float4(p[12], p[13], p[14], p[15]);

        __syncwarp();
        __threadfence_block();
        if (t == 0) flg[w] = k + 1;
    }

    // per-image max
    #pragma unroll
    for (int d = 16; d > 0; d >>= 1)
        lmax = fmaxf(lmax, __shfl_xor_sync(FM, lmax, d));
    if (t == 0) lred[w] = lmax;
    __syncthreads();
    if (threadIdx.x == 0) {
        float mm = 0.0f;
        #pragma unroll
        for (int i = 0; i < 16; i++) mm = fmaxf(mm, lred[i]);
        g_mx[img] = mm;
    }
}

// ---------------- loss partial sums ----------------
__global__ __launch_bounds__(LBLK) void loss_partial(const float* __restrict__ pred,
                                                     const int* __restrict__ target) {
    const int img = blockIdx.x / BPI;
    const int sub = blockIdx.x % BPI;
    const int base = img * NPIX;
    const float mx = g_mx[img];
    const int hfg = g_flags[img] & 1;
    const float inv = 1.0f / fmaxf(mx, 1e-12f);
    const int usediv = (mx > 0.0f) ? 1 : 0;

    float sF = 0.f, sB = 0.f, sP = 0.f, sT = 0.f, sPT = 0.f;
    for (int idx = sub * LBLK + threadIdx.x; idx < NPIX; idx += BPI * LBLK) {
        float x = pred[base + idx];
        int tv = target[base + idx];
        float d = g_dist[base + idx];
        float p = 1.0f / (1.0f + expf(-x));
        float ax = fabsf(x);
        float bce = log1pf(expf(-ax)) + (tv ? fmaxf(-x, 0.0f) : fmaxf(x, 0.0f));
        float pt = tv ? p : (1.0f - p);
        float omp = 1.0f - pt;
        float alpha = tv ? 0.25f : 0.75f;
        sF += alpha * omp * omp * bce;
        float dn = hfg ? (usediv ? d * inv : d) : 1.0f;
        sB += omp * (1.0f + dn);
        sP += p;
        if (tv) { sT += 1.0f; sPT += p; }
    }

    float vals[5] = {sF, sB, sP, sT, sPT};
    #pragma unroll
    for (int k = 0; k < 5; k++) {
        float v = vals[k];
        #pragma unroll
        for (int d = 16; d > 0; d >>= 1) v += __shfl_xor_sync(0xffffffffu, v, d);
        vals[k] = v;
    }
    __shared__ float s5[LBLK / 32][5];
    int lane = threadIdx.x & 31, wid = threadIdx.x >> 5;
    if (lane == 0) {
        #pragma unroll
        for (int k = 0; k < 5; k++) s5[wid][k] = vals[k];
    }
    __syncthreads();
    if (threadIdx.x == 0) {
        #pragma unroll
        for (int k = 0; k < 5; k++) {
            float a = 0.f;
            for (int w = 0; w < LBLK / 32; w++) a += s5[w][k];
            g_part[blockIdx.x * 5 + k] = a;
        }
    }
}

// ---------------- final combine ----------------
__global__ void loss_final(const float* __restrict__ lv, float* __restrict__ out,
                           int out_size) {
    __shared__ double sd[BATCH][4];
    int t = threadIdx.x;
    if (t < BATCH) {
        double F = 0, Bd = 0, P = 0, T = 0, PT = 0;
        for (int b = 0; b < BPI; b++) {
            const float* pp = g_part + (t * BPI + b) * 5;
            F += pp[0]; Bd += pp[1]; P += pp[2]; T += pp[3]; PT += pp[4];
        }
        double total = P + T;
        double uni = total - PT;
        sd[t][0] = F;
        sd[t][1] = Bd;
        sd[t][2] = (2.0 * PT + 1e-6) / (total + 1e-6);
        sd[t][3] = (PT + 1e-6) / (uni + 1e-6);
    }
    __syncthreads();
    if (t == 0) {
        double F = 0, Bd = 0, D = 0, I = 0;
        for (int b = 0; b < BATCH; b++) {
            F += sd[b][0]; Bd += sd[b][1]; D += sd[b][2]; I += sd[b][3];
        }
        double N = (double)BATCH * (double)NPIX;
        double focal = F / N;
        double bnd   = Bd / N;
        double dice  = 1.0 - D / (double)BATCH;
        double iou   = 1.0 - I / (double)BATCH;
        double l0 = (double)lv[0], l1 = (double)lv[1], l2 = (double)lv[2], l3 = (double)lv[3];
        double tot = exp(-l0) * focal + l0
                   + exp(-l1) * dice  + l1
                   + exp(-l2) * bnd   + l2
                   + exp(-l3) * iou   + l3;
        if (out_size > 0) out[0] = (float)tot;
        if (out_size > 1) out[1] = (float)focal;
        if (out_size > 2) out[2] = (float)dice;
        if (out_size > 3) out[3] = (float)bnd;
        if (out_size > 4) out[4] = (float)iou;
    }
}

extern "C" void kernel_launch(void* const* d_in, const int* in_sizes, int n_in,
                              void* d_out, int out_size) {
    const float* pred   = (const float*)d_in[0];
    const int*   target = (const int*)d_in[1];
    const float* lv     = (const float*)d_in[2];
    float* out = (float*)d_out;

    seed_kernel<<<BATCH, 128>>>(target);
    dt_pipe_kernel<<<BATCH, 512>>>();
    loss_partial<<<NLB, LBLK>>>(pred, target);
    loss_final<<<1, 32>>>(lv, out, out_size);
}

// round 8
// speedup vs baseline: 1.8094x; 1.8094x over previous
#include <cuda_runtime.h>
#include <cuda_bf16.h>
#include <math.h>

#define H 512
#define W 512
#define BATCH 16
#define NPIX (H*W)
#define CA 0.955f
#define CB 1.3693f
#define CINF 1e6f
#define BIG 1e30f

#define LBLK 256
#define BPI 16
#define NLB (BATCH*BPI)

// ---------------- device scratch ----------------
__device__ float    g_dist[BATCH*NPIX];
__device__ float    g_mx[BATCH];
__device__ int      g_flags[BATCH];
__device__ float    g_part[NLB*5];
__device__ unsigned g_seed[BATCH*H*16];   // 512 KB seed bitmaps

// =============== seed kernel: bitmap + dilate/erode -> seed bits ===============
__global__ __launch_bounds__(128) void seed_kernel(const int* __restrict__ target) {
    __shared__ unsigned mbits[H * 18];
    __shared__ int sflag[2];

    const int img = blockIdx.x;
    const int* tg = target + img * NPIX;
    unsigned* sb = g_seed + img * H * 16;

    const int tid  = threadIdx.x;
    const int lane = tid & 31;
    const int sl   = tid & 7;
    const int sg   = tid >> 3;
    const int col0 = tid * 4;
    const unsigned FM = 0xffffffffu;

    if (tid < 2) sflag[tid] = 0;
    for (int r = tid; r < H; r += 128) {
        mbits[r * 18 + 0]  = 0u;
        mbits[r * 18 + 17] = 0u;
    }
    __syncthreads();

    bool any1 = false, any0 = false;
    for (int r = 0; r < H; r++) {
        int4 tv = *(const int4*)(tg + r * W + col0);
        unsigned nib = (unsigned)(tv.x != 0) | ((unsigned)(tv.y != 0) << 1)
                     | ((unsigned)(tv.z != 0) << 2) | ((unsigned)(tv.w != 0) << 3);
        any1 |= (nib != 0u);
        any0 |= (nib != 15u);
        unsigned word = nib << (4 * sl);
        word |= __shfl_xor_sync(FM, word, 1);
        word |= __shfl_xor_sync(FM, word, 2);
        word |= __shfl_xor_sync(FM, word, 4);
        if (sl == 0) mbits[r * 18 + 1 + sg] = word;
    }
    if (__any_sync(FM, any1) && lane == 0) atomicOr(&sflag[0], 1);
    if (__any_sync(FM, any0) && lane == 0) atomicOr(&sflag[1], 1);
    __syncthreads();
    const int hasb = sflag[0] & sflag[1];

    for (int idx = tid; idx < H * 16; idx += 128) {
        int r = idx >> 4, w = idx & 15;
        unsigned swd;
        if (hasb) {
            unsigned dil = 0u, ero = 0xffffffffu;
            #pragma unroll
            for (int dr = -1; dr <= 1; dr++) {
                int r2 = r + dr;
                if (r2 < 0 || r2 >= H) continue;
                unsigned M  = mbits[r2 * 18 + 1 + w];
                unsigned Ml = mbits[r2 * 18 + w];
                unsigned Mr = mbits[r2 * 18 + 2 + w];
                unsigned Mlg = (w == 0)  ? 0xffffffffu : Ml;
                unsigned Mrg = (w == 15) ? 0xffffffffu : Mr;
                dil |= M | __funnelshift_l(Ml, M, 1) | __funnelshift_r(M, Mr, 1);
                ero &= M & __funnelshift_l(Mlg, M, 1) & __funnelshift_r(M, Mrg, 1);
            }
            swd = dil & ~ero;
        } else {
            swd = ~mbits[r * 18 + 1 + w];
        }
        sb[idx] = swd;
    }
    if (tid == 0) g_flags[img] = sflag[0] | (sflag[1] << 1);
}

// ---------------- warp-scan helpers (bit-exact, from passing R5 kernel) ----------------
__device__ __forceinline__ float scan_up(float x, int t) {
    const unsigned FM = 0xffffffffu;
    float o;
    o = __shfl_up_sync(FM, x, 1);  if (t >= 1)  x = fminf(x, o);
    o = __shfl_up_sync(FM, x, 2);  if (t >= 2)  x = fminf(x, o);
    o = __shfl_up_sync(FM, x, 4);  if (t >= 4)  x = fminf(x, o);
    o = __shfl_up_sync(FM, x, 8);  if (t >= 8)  x = fminf(x, o);
    o = __shfl_up_sync(FM, x, 16); if (t >= 16) x = fminf(x, o);
    return x;
}
__device__ __forceinline__ float scan_dn(float x, int t) {
    const unsigned FM = 0xffffffffu;
    float o;
    o = __shfl_down_sync(FM, x, 1);  if (t <= 30) x = fminf(x, o);
    o = __shfl_down_sync(FM, x, 2);  if (t <= 29) x = fminf(x, o);
    o = __shfl_down_sync(FM, x, 4);  if (t <= 27) x = fminf(x, o);
    o = __shfl_down_sync(FM, x, 8);  if (t <= 23) x = fminf(x, o);
    o = __shfl_down_sync(FM, x, 16); if (t <= 15) x = fminf(x, o);
    return x;
}

// forward m+v computation (v = m - aj, via +naj; all fmins exact)
__device__ __forceinline__ void fwd_mv(const float* p, float pvL, float pvR,
                                       unsigned hw, const float* naj, float* v) {
    #pragma unroll
    for (int c = 0; c < 16; c++) {
        float pl = (c == 0)  ? pvL : p[c - 1];
        float pr = (c == 15) ? pvR : p[c + 1];
        float dv = ((hw >> c) & 1u) ? 0.0f : CINF;
        float t1 = p[c] + CA;
        float t3 = fminf(pl, pr) + CB;
        float m  = fminf(fminf(t1, t3), dv);
        v[c] = m + naj[c];
    }
}
// backward m+v (drw instead of seed)
__device__ __forceinline__ void bwd_mv(const float* p, float pvL, float pvR,
                                       const float* drw, const float* nar, float* v) {
    #pragma unroll
    for (int c = 0; c < 16; c++) {
        float pl = (c == 0)  ? pvL : p[c - 1];
        float pr = (c == 15) ? pvR : p[c + 1];
        float t1 = p[c] + CA;
        float t3 = fminf(pl, pr) + CB;
        float m  = fminf(fminf(t1, t3), drw[c]);
        v[c] = m + nar[c];
    }
}

// =============== dt kernel: ONE WARP handles TWO images (fills scan bubbles) ===============
__global__ __launch_bounds__(32) void dt_warp2_kernel() {
    const int pair = blockIdx.x;              // 0..7
    const int imgA = 2 * pair, imgB = 2 * pair + 1;
    const unsigned* sbA = g_seed + imgA * H * 16;
    const unsigned* sbB = g_seed + imgB * H * 16;
    float* ddA = g_dist + imgA * NPIX;
    float* ddB = g_dist + imgB * NPIX;

    const int t  = threadIdx.x;
    const int c0 = t * 16;
    const unsigned FM = 0xffffffffu;
    const int wsel = t >> 1;
    const int wsh  = (t & 1) * 16;

    float aj[16], naj[16];
    #pragma unroll
    for (int c = 0; c < 16; c++) { aj[c] = CA * (float)(c0 + c); naj[c] = -aj[c]; }
    const float ajL = CA * (float)(c0 - 1);
    const float ajR = CA * (float)(c0 + 16);

    // ================= forward pass (both images) =================
    float pA[16], pB[16];
    #pragma unroll
    for (int c = 0; c < 16; c++) { pA[c] = CINF; pB[c] = CINF; }
    float pvLA = CINF, pvRA = CINF, pvLB = CINF, pvRB = CINF;

    unsigned hwA = (sbA[wsel] >> wsh) & 0xffffu;
    unsigned hwB = (sbB[wsel] >> wsh) & 0xffffu;

    for (int i = 0; i < H; i++) {
        unsigned hnA = 0u, hnB = 0u;
        if (i < H - 1) {
            hnA = (sbA[(i + 1) * 16 + wsel] >> wsh) & 0xffffu;
            hnB = (sbB[(i + 1) * 16 + wsel] >> wsh) & 0xffffu;
        }

        float vA[16], vB[16];
        fwd_mv(pA, pvLA, pvRA, hwA, naj, vA);
        fwd_mv(pB, pvLB, pvRB, hwB, naj, vB);
        float vR0A = __shfl_down_sync(FM, vA[0], 1);
        float vR0B = __shfl_down_sync(FM, vB[0], 1);

        #pragma unroll
        for (int c = 1; c < 16; c++) vA[c] = fminf(vA[c - 1], vA[c]);
        #pragma unroll
        for (int c = 1; c < 16; c++) vB[c] = fminf(vB[c - 1], vB[c]);

        float sAv = scan_up(vA[15], t);
        float sBv = scan_up(vB[15], t);
        float exA = __shfl_up_sync(FM, sAv, 1); if (t == 0) exA = BIG;
        float exB = __shfl_up_sync(FM, sBv, 1); if (t == 0) exB = BIG;

        #pragma unroll
        for (int c = 0; c < 16; c++) pA[c] = aj[c] + fminf(exA, vA[c]);
        #pragma unroll
        for (int c = 0; c < 16; c++) pB[c] = aj[c] + fminf(exB, vB[c]);

        float* rowA = ddA + i * W + c0;
        *(float4*)(rowA + 0)  = make_float4(pA[0],  pA[1],  pA[2],  pA[3]);
        *(float4*)(rowA + 4)  = make_float4(pA[4],  pA[5],  pA[6],  pA[7]);
        *(float4*)(rowA + 8)  = make_float4(pA[8],  pA[9],  pA[10], pA[11]);
        *(float4*)(rowA + 12) = make_float4(pA[12], pA[13], pA[14], pA[15]);
        float* rowB = ddB + i * W + c0;
        *(float4*)(rowB + 0)  = make_float4(pB[0],  pB[1],  pB[2],  pB[3]);
        *(float4*)(rowB + 4)  = make_float4(pB[4],  pB[5],  pB[6],  pB[7]);
        *(float4*)(rowB + 8)  = make_float4(pB[8],  pB[9],  pB[10], pB[11]);
        *(float4*)(rowB + 12) = make_float4(pB[12], pB[13], pB[14], pB[15]);

        pvLA = (t == 0)  ? CINF : (ajL + exA);
        pvRA = (t == 31) ? CINF : (ajR + fminf(sAv, vR0A));
        pvLB = (t == 0)  ? CINF : (ajL + exB);
        pvRB = (t == 31) ? CINF : (ajR + fminf(sBv, vR0B));
        hwA = hnA; hwB = hnB;
    }

    // ================= backward pass (both images) =================
    float ar[16], nar[16];
    #pragma unroll
    for (int c = 0; c < 16; c++) { ar[c] = CA * (float)(W - 1 - (c0 + c)); nar[c] = -ar[c]; }
    const float arL = CA * (float)(W - c0);
    const float arR = CA * (float)(W - 17 - c0);

    #pragma unroll
    for (int c = 0; c < 16; c++) { pA[c] = CINF; pB[c] = CINF; }
    pvLA = CINF; pvRA = CINF; pvLB = CINF; pvRB = CINF;
    float lmA = 0.0f, lmB = 0.0f;

    float4 a0, a1, a2, a3, b0, b1, b2, b3;
    {
        const float* rA = ddA + (H - 1) * W + c0;
        a0 = *(const float4*)(rA + 0); a1 = *(const float4*)(rA + 4);
        a2 = *(const float4*)(rA + 8); a3 = *(const float4*)(rA + 12);
        const float* rB = ddB + (H - 1) * W + c0;
        b0 = *(const float4*)(rB + 0); b1 = *(const float4*)(rB + 4);
        b2 = *(const float4*)(rB + 8); b3 = *(const float4*)(rB + 12);
    }

    for (int i = H - 1; i >= 0; i--) {
        float drA[16] = {a0.x,a0.y,a0.z,a0.w, a1.x,a1.y,a1.z,a1.w,
                         a2.x,a2.y,a2.z,a2.w, a3.x,a3.y,a3.z,a3.w};
        float drB[16] = {b0.x,b0.y,b0.z,b0.w, b1.x,b1.y,b1.z,b1.w,
                         b2.x,b2.y,b2.z,b2.w, b3.x,b3.y,b3.z,b3.w};
        if (i > 0) {
            const float* rA = ddA + (i - 1) * W + c0;
            a0 = *(const float4*)(rA + 0); a1 = *(const float4*)(rA + 4);
            a2 = *(const float4*)(rA + 8); a3 = *(const float4*)(rA + 12);
            const float* rB = ddB + (i - 1) * W + c0;
            b0 = *(const float4*)(rB + 0); b1 = *(const float4*)(rB + 4);
            b2 = *(const float4*)(rB + 8); b3 = *(const float4*)(rB + 12);
        }

        float vA[16], vB[16];
        bwd_mv(pA, pvLA, pvRA, drA, nar, vA);
        bwd_mv(pB, pvLB, pvRB, drB, nar, vB);
        float vL15A = __shfl_up_sync(FM, vA[15], 1);
        float vL15B = __shfl_up_sync(FM, vB[15], 1);

        #pragma unroll
        for (int c = 14; c >= 0; c--) vA[c] = fminf(vA[c], vA[c + 1]);
        #pragma unroll
        for (int c = 14; c >= 0; c--) vB[c] = fminf(vB[c], vB[c + 1]);

        float sAv = scan_dn(vA[0], t);
        float sBv = scan_dn(vB[0], t);
        float exA = __shfl_down_sync(FM, sAv, 1); if (t == 31) exA = BIG;
        float exB = __shfl_down_sync(FM, sBv, 1); if (t == 31) exB = BIG;

        #pragma unroll
        for (int c = 0; c < 16; c++) { pA[c] = ar[c] + fminf(exA, vA[c]); lmA = fmaxf(lmA, pA[c]); }
        #pragma unroll
        for (int c = 0; c < 16; c++) { pB[c] = ar[c] + fminf(exB, vB[c]); lmB = fmaxf(lmB, pB[c]); }

        float* rowA = ddA + i * W + c0;
        *(float4*)(rowA + 0)  = make_float4(pA[0],  pA[1],  pA[2],  pA[3]);
        *(float4*)(rowA + 4)  = make_float4(pA[4],  pA[5],  pA[6],  pA[7]);
        *(float4*)(rowA + 8)  = make_float4(pA[8],  pA[9],  pA[10], pA[11]);
        *(float4*)(rowA + 12) = make_float4(pA[12], pA[13], pA[14], pA[15]);
        float* rowB = ddB + i * W + c0;
        *(float4*)(rowB + 0)  = make_float4(pB[0],  pB[1],  pB[2],  pB[3]);
        *(float4*)(rowB + 4)  = make_float4(pB[4],  pB[5],  pB[6],  pB[7]);
        *(float4*)(rowB + 8)  = make_float4(pB[8],  pB[9],  pB[10], pB[11]);
        *(float4*)(rowB + 12) = make_float4(pB[12], pB[13], pB[14], pB[15]);

        pvRA = (t == 31) ? CINF : (arR + exA);
        pvLA = (t == 0)  ? CINF : (arL + fminf(sAv, vL15A));
        pvRB = (t == 31) ? CINF : (arR + exB);
        pvLB = (t == 0)  ? CINF : (arL + fminf(sBv, vL15B));
    }

    // per-image max
    #pragma unroll
    for (int d = 16; d > 0; d >>= 1) {
        lmA = fmaxf(lmA, __shfl_xor_sync(FM, lmA, d));
        lmB = fmaxf(lmB, __shfl_xor_sync(FM, lmB, d));
    }
    if (t == 0) { g_mx[imgA] = lmA; g_mx[imgB] = lmB; }
}

// ---------------- loss partial sums ----------------
__global__ __launch_bounds__(LBLK) void loss_partial(const float* __restrict__ pred,
                                                     const int* __restrict__ target) {
    const int img = blockIdx.x / BPI;
    const int sub = blockIdx.x % BPI;
    const int base = img * NPIX;
    const float mx = g_mx[img];
    const int hfg = g_flags[img] & 1;
    const float inv = 1.0f / fmaxf(mx, 1e-12f);
    const int usediv = (mx > 0.0f) ? 1 : 0;

    float sF = 0.f, sB = 0.f, sP = 0.f, sT = 0.f, sPT = 0.f;
    for (int idx = sub * LBLK + threadIdx.x; idx < NPIX; idx += BPI * LBLK) {
        float x = pred[base + idx];
        int tv = target[base + idx];
        float d = g_dist[base + idx];
        float p = 1.0f / (1.0f + expf(-x));
        float ax = fabsf(x);
        float bce = log1pf(expf(-ax)) + (tv ? fmaxf(-x, 0.0f) : fmaxf(x, 0.0f));
        float pt = tv ? p : (1.0f - p);
        float omp = 1.0f - pt;
        float alpha = tv ? 0.25f : 0.75f;
        sF += alpha * omp * omp * bce;
        float dn = hfg ? (usediv ? d * inv : d) : 1.0f;
        sB += omp * (1.0f + dn);
        sP += p;
        if (tv) { sT += 1.0f; sPT += p; }
    }

    float vals[5] = {sF, sB, sP, sT, sPT};
    #pragma unroll
    for (int k = 0; k < 5; k++) {
        float v = vals[k];
        #pragma unroll
        for (int d = 16; d > 0; d >>= 1) v += __shfl_xor_sync(0xffffffffu, v, d);
        vals[k] = v;
    }
    __shared__ float s5[LBLK / 32][5];
    int lane = threadIdx.x & 31, wid = threadIdx.x >> 5;
    if (lane == 0) {
        #pragma unroll
        for (int k = 0; k < 5; k++) s5[wid][k] = vals[k];
    }
    __syncthreads();
    if (threadIdx.x == 0) {
        #pragma unroll
        for (int k = 0; k < 5; k++) {
            float a = 0.f;
            for (int w = 0; w < LBLK / 32; w++) a += s5[w][k];
            g_part[blockIdx.x * 5 + k] = a;
        }
    }
}

// ---------------- final combine ----------------
__global__ void loss_final(const float* __restrict__ lv, float* __restrict__ out,
                           int out_size) {
    __shared__ double sd[BATCH][4];
    int t = threadIdx.x;
    if (t < BATCH) {
        double F = 0, Bd = 0, P = 0, T = 0, PT = 0;
        for (int b = 0; b < BPI; b++) {
            const float* pp = g_part + (t * BPI + b) * 5;
            F += pp[0]; Bd += pp[1]; P += pp[2]; T += pp[3]; PT += pp[4];
        }
        double total = P + T;
        double uni = total - PT;
        sd[t][0] = F;
        sd[t][1] = Bd;
        sd[t][2] = (2.0 * PT + 1e-6) / (total + 1e-6);
        sd[t][3] = (PT + 1e-6) / (uni + 1e-6);
    }
    __syncthreads();
    if (t == 0) {
        double F = 0, Bd = 0, D = 0, I = 0;
        for (int b = 0; b < BATCH; b++) {
            F += sd[b][0]; Bd += sd[b][1]; D += sd[b][2]; I += sd[b][3];
        }
        double N = (double)BATCH * (double)NPIX;
        double focal = F / N;
        double bnd   = Bd / N;
        double dice  = 1.0 - D / (double)BATCH;
        double iou   = 1.0 - I / (double)BATCH;
        double l0 = (double)lv[0], l1 = (double)lv[1], l2 = (double)lv[2], l3 = (double)lv[3];
        double tot = exp(-l0) * focal + l0
                   + exp(-l1) * dice  + l1
                   + exp(-l2) * bnd   + l2
                   + exp(-l3) * iou   + l3;
        if (out_size > 0) out[0] = (float)tot;
        if (out_size > 1) out[1] = (float)focal;
        if (out_size > 2) out[2] = (float)dice;
        if (out_size > 3) out[3] = (float)bnd;
        if (out_size > 4) out[4] = (float)iou;
    }
}

extern "C" void kernel_launch(void* const* d_in, const int* in_sizes, int n_in,
                              void* d_out, int out_size) {
    const float* pred   = (const float*)d_in[0];
    const int*   target = (const int*)d_in[1];
    const float* lv     = (const float*)d_in[2];
    float* out = (float*)d_out;

    seed_kernel<<<BATCH, 128>>>(target);
    dt_warp2_kernel<<<BATCH / 2, 32>>>();
    loss_partial<<<NLB, LBLK>>>(pred, target);
    loss_final<<<1, 32>>>(lv, out, out_size);
}